// round 15
// baseline (speedup 1.0000x reference)
#include <cuda_runtime.h>

// ---------------------------------------------------------------------------
// NodeModule_4432406249918  (GB300 / sm_103a)
//   Kernel A: fused reduce + section-per-block fill.
//     - Reduce blocks: R5/R14-identical column reductions -> transposed partials.
//     - Fill blocks: each owns ONE output section (block b of array a, or the
//       degree section). b is block-uniform; per thread: load interval once,
//       then `half/256` sequential STG.128 of ones with <=1 special float4.
//   Kernel B: warp-per-column finalize (R5-identical) writes coeff rows.
//
// out = [ input_under ((n+1)*n,2) | input_over ((n+1)*n,2) | ones(n) | ones(n) ]
//   under_coeffs[j] = sum_k ( nw[k]*Over[k][j] + pw[k]*Under[k][j] ) + bias
//   over_coeffs [j] = sum_k ( pw[k]*Over[k][j] + nw[k]*Under[k][j] ) + bias
//   block b, row i, col c:
//     i==0           -> coeffs[b] * (b==0 ? intervals[0][c] : 1)
//     i==b (0<i<n)   -> intervals[i][c]
//     else           -> 1
//
// Section layout (per array, block b = `half` float4s):
//   fi==0       : floats {coeff,coeff, row1} -> placeholder ones; if b==1 the
//                 z,w lanes are intervals[1]
//   fi==b>>1    : (b>=2) even b -> x,y = intervals[b]; odd b -> z,w = intervals[b]
//   otherwise   : {1,1,1,1}
// ---------------------------------------------------------------------------

#define KSPLIT 64
#define MAXC   8192   // >= n_vars+1

// transposed: g_part_*[j * KSPLIT + y]  (finalize reads coalesce per warp)
__device__ float g_part_u[MAXC * KSPLIT];
__device__ float g_part_o[MAXC * KSPLIT];

// ---- Kernel A: fused partial reductions + section fill ----------------------
__global__ void __launch_bounds__(256) fused_reduce_fill(
    const float* __restrict__ U,
    const float* __restrict__ O,
    const float* __restrict__ pw,
    const float* __restrict__ nw,
    const float2* __restrict__ itv,
    float* __restrict__ out,
    int K, int ncols, int rpb, int RX, unsigned RBLOCKS,
    unsigned half, unsigned nsec)
{
    unsigned bid = blockIdx.x;

    if (bid < RBLOCKS) {
        // ---------------- reduction part (read-bound) — R5-identical ---------
        int bx = (int)(bid % (unsigned)RX);
        int by = (int)(bid / (unsigned)RX);
        int j  = bx * 256 + (int)threadIdx.x;
        if (j >= ncols) return;
        int k0 = by * rpb;
        int k1 = min(k0 + rpb, K);

        float au0 = 0.f, au1 = 0.f, ao0 = 0.f, ao1 = 0.f;
        size_t base = (size_t)k0 * (size_t)ncols + (size_t)j;
        int k = k0;
        #pragma unroll 4
        for (; k + 1 < k1; k += 2, base += 2 * (size_t)ncols) {
            float u0 = __ldg(U + base);
            float o0 = __ldg(O + base);
            float u1 = __ldg(U + base + ncols);
            float o1 = __ldg(O + base + ncols);
            float p0 = __ldg(pw + k);
            float n0 = __ldg(nw + k);
            float p1 = __ldg(pw + k + 1);
            float n1 = __ldg(nw + k + 1);
            au0 = fmaf(p0, u0, au0);  au0 = fmaf(n0, o0, au0);
            ao0 = fmaf(n0, u0, ao0);  ao0 = fmaf(p0, o0, ao0);
            au1 = fmaf(p1, u1, au1);  au1 = fmaf(n1, o1, au1);
            ao1 = fmaf(n1, u1, ao1);  ao1 = fmaf(p1, o1, ao1);
        }
        if (k < k1) {
            float u = __ldg(U + base), o = __ldg(O + base);
            float p = __ldg(pw + k),   n = __ldg(nw + k);
            au0 = fmaf(p, u, au0);  au0 = fmaf(n, o, au0);
            ao0 = fmaf(n, u, ao0);  ao0 = fmaf(p, o, ao0);
        }
        // keep partials L2-resident for the finalize
        __stcg(&g_part_u[(size_t)j * KSPLIT + by], au0 + au1);
        __stcg(&g_part_o[(size_t)j * KSPLIT + by], ao0 + ao1);
        return;
    }

    // ---------------- fill part: one section per block -----------------------
    unsigned s = bid - RBLOCKS;                 // section index (< nsec)
    float4* dst = reinterpret_cast<float4*>(out) + (size_t)s * half;
    unsigned chunks = half >> 8;                // stores per thread
    unsigned tid = threadIdx.x;

    if (s < nsec - 1u) {                        // ibf sections (under then over)
        unsigned b  = s;                        // block index within array
        if (b >= (unsigned)ncols) b -= (unsigned)ncols;
        unsigned fs = b >> 1;                   // special float4 (rows b), b>=2
        float2 tb = make_float2(1.f, 1.f);
        if (b >= 1u) tb = __ldg(itv + b);       // interval for row b

        bool odd = (b & 1u) != 0u;
        #pragma unroll 8
        for (unsigned c = 0; c < chunks; ++c) {
            unsigned fi = c * 256u + tid;
            float4 v = make_float4(1.f, 1.f, 1.f, 1.f);
            if (b >= 2u) {
                if (fi == fs) {
                    if (odd) { v.z = tb.x; v.w = tb.y; }
                    else     { v.x = tb.x; v.y = tb.y; }
                }
            } else if (b == 1u && fi == 0u) {
                v.z = tb.x; v.w = tb.y;         // row 1 of block 1 = intervals[1]
            }
            // fi==0 x,y: coeff placeholder (overwritten by finalize)
            __stcs(dst + fi, v);
        }
    } else {                                    // degree section: all ones
        float4 v = make_float4(1.f, 1.f, 1.f, 1.f);
        #pragma unroll 8
        for (unsigned c = 0; c < chunks; ++c)
            __stcs(dst + c * 256u + tid, v);
    }
}

// ---- Kernel B: warp-per-column fold + bias + coeff rows (R5-identical) -----
__global__ void __launch_bounds__(256) finalize(
    const float* __restrict__ bias,
    const float2* __restrict__ itv,
    float* __restrict__ out,
    int ncols, int n_vars)
{
    int warp = (blockIdx.x * 256 + threadIdx.x) >> 5;   // one warp per column
    int lane = threadIdx.x & 31;
    if (warp >= ncols) return;
    int j = warp;

    const float* pu = g_part_u + (size_t)j * KSPLIT;
    const float* po = g_part_o + (size_t)j * KSPLIT;
    float su = __ldg(pu + lane) + __ldg(pu + lane + 32);
    float so = __ldg(po + lane) + __ldg(po + lane + 32);

    #pragma unroll
    for (int off = 16; off > 0; off >>= 1) {
        su += __shfl_xor_sync(0xFFFFFFFFu, su, off);
        so += __shfl_xor_sync(0xFFFFFFFFu, so, off);
    }

    if (lane == 0) {
        float bs = bias[0];
        su += bs;  so += bs;

        float2 vu, vo;
        if (j == 0) {
            float2 t0 = __ldg(itv);
            vu = make_float2(su * t0.x, su * t0.y);
            vo = make_float2(so * t0.x, so * t0.y);
        } else {
            vu = make_float2(su, su);
            vo = make_float2(so, so);
        }

        size_t NE2 = (size_t)ncols * (size_t)n_vars;   // float2s per ibf array
        float2* o2 = reinterpret_cast<float2*>(out);
        o2[(size_t)j * (size_t)n_vars]       = vu;
        o2[NE2 + (size_t)j * (size_t)n_vars] = vo;
    }
}

// ---------------------------------------------------------------------------
extern "C" void kernel_launch(void* const* d_in, const int* in_sizes, int n_in,
                              void* d_out, int out_size)
{
    const float* U    = (const float*)d_in[0];   // layer_inputs_under  (K, n+1)
    const float* O    = (const float*)d_in[1];   // layer_inputs_over   (K, n+1)
    const float* itv  = (const float*)d_in[4];   // intervals (n, 2)
    const float* pw   = (const float*)d_in[5];   // node_pos_weights (K,)
    const float* nw   = (const float*)d_in[6];   // node_neg_weights (K,)
    const float* bias = (const float*)d_in[7];   // node_bias (1,)
    float* out = (float*)d_out;

    const int n_vars = in_sizes[2];              // 4096
    const int K      = in_sizes[5];              // 4096
    const int ncols  = n_vars + 1;

    // reduction geometry
    const int RX  = (ncols + 255) / 256;
    const int rpb = (K + KSPLIT - 1) / KSPLIT;
    const unsigned RBLOCKS = (unsigned)(RX * KSPLIT);

    // fill geometry: one section = `half` float4s = one output block (or the
    // combined degree vectors, which total exactly `half` float4s as well).
    unsigned half = (unsigned)(n_vars >> 1);               // float4s per section
    unsigned nsec = (unsigned)(2 * ncols) + 1u;            // 2*ncols ibf + 1 degree

    dim3 gridA(RBLOCKS + nsec);
    fused_reduce_fill<<<gridA, 256>>>(U, O, pw, nw, (const float2*)itv, out,
                                      K, ncols, rpb, RX, RBLOCKS,
                                      half, nsec);

    // one warp per column
    int finThreads = ncols * 32;
    finalize<<<(finThreads + 255) / 256, 256>>>(bias, (const float2*)itv, out,
                                                ncols, n_vars);
}

// round 16
// speedup vs baseline: 1.0038x; 1.0038x over previous
#include <cuda_runtime.h>

// ---------------------------------------------------------------------------
// NodeModule_4432406249918  (GB300 / sm_103a)
//   Kernel A: fused reduce + section-per-block fill (R15-identical, best A).
//   Kernel B: finalize, warp-per-TWO-columns (8 independent loads/thread to
//             hide DRAM latency under kernel A's writeback drain).
//
// out = [ input_under ((n+1)*n,2) | input_over ((n+1)*n,2) | ones(n) | ones(n) ]
//   under_coeffs[j] = sum_k ( nw[k]*Over[k][j] + pw[k]*Under[k][j] ) + bias
//   over_coeffs [j] = sum_k ( pw[k]*Over[k][j] + nw[k]*Under[k][j] ) + bias
//   block b, row i, col c:
//     i==0           -> coeffs[b] * (b==0 ? intervals[0][c] : 1)
//     i==b (0<i<n)   -> intervals[i][c]
//     else           -> 1
// ---------------------------------------------------------------------------

#define KSPLIT 64
#define MAXC   8192   // >= n_vars+1

// transposed: g_part_*[j * KSPLIT + y]  (finalize reads coalesce per warp)
__device__ float g_part_u[MAXC * KSPLIT];
__device__ float g_part_o[MAXC * KSPLIT];

// ---- Kernel A: fused partial reductions + section fill (R15-identical) ------
__global__ void __launch_bounds__(256) fused_reduce_fill(
    const float* __restrict__ U,
    const float* __restrict__ O,
    const float* __restrict__ pw,
    const float* __restrict__ nw,
    const float2* __restrict__ itv,
    float* __restrict__ out,
    int K, int ncols, int rpb, int RX, unsigned RBLOCKS,
    unsigned half, unsigned nsec)
{
    unsigned bid = blockIdx.x;

    if (bid < RBLOCKS) {
        // ---------------- reduction part (read-bound) ----------------
        int bx = (int)(bid % (unsigned)RX);
        int by = (int)(bid / (unsigned)RX);
        int j  = bx * 256 + (int)threadIdx.x;
        if (j >= ncols) return;
        int k0 = by * rpb;
        int k1 = min(k0 + rpb, K);

        float au0 = 0.f, au1 = 0.f, ao0 = 0.f, ao1 = 0.f;
        size_t base = (size_t)k0 * (size_t)ncols + (size_t)j;
        int k = k0;
        #pragma unroll 4
        for (; k + 1 < k1; k += 2, base += 2 * (size_t)ncols) {
            float u0 = __ldg(U + base);
            float o0 = __ldg(O + base);
            float u1 = __ldg(U + base + ncols);
            float o1 = __ldg(O + base + ncols);
            float p0 = __ldg(pw + k);
            float n0 = __ldg(nw + k);
            float p1 = __ldg(pw + k + 1);
            float n1 = __ldg(nw + k + 1);
            au0 = fmaf(p0, u0, au0);  au0 = fmaf(n0, o0, au0);
            ao0 = fmaf(n0, u0, ao0);  ao0 = fmaf(p0, o0, ao0);
            au1 = fmaf(p1, u1, au1);  au1 = fmaf(n1, o1, au1);
            ao1 = fmaf(n1, u1, ao1);  ao1 = fmaf(p1, o1, ao1);
        }
        if (k < k1) {
            float u = __ldg(U + base), o = __ldg(O + base);
            float p = __ldg(pw + k),   n = __ldg(nw + k);
            au0 = fmaf(p, u, au0);  au0 = fmaf(n, o, au0);
            ao0 = fmaf(n, u, ao0);  ao0 = fmaf(p, o, ao0);
        }
        // keep partials L2-resident for the finalize
        __stcg(&g_part_u[(size_t)j * KSPLIT + by], au0 + au1);
        __stcg(&g_part_o[(size_t)j * KSPLIT + by], ao0 + ao1);
        return;
    }

    // ---------------- fill part: one section per block -----------------------
    unsigned s = bid - RBLOCKS;                 // section index (< nsec)
    float4* dst = reinterpret_cast<float4*>(out) + (size_t)s * half;
    unsigned chunks = half >> 8;                // stores per thread
    unsigned tid = threadIdx.x;

    if (s < nsec - 1u) {                        // ibf sections (under then over)
        unsigned b  = s;                        // block index within array
        if (b >= (unsigned)ncols) b -= (unsigned)ncols;
        unsigned fs = b >> 1;                   // special float4 (rows b), b>=2
        float2 tb = make_float2(1.f, 1.f);
        if (b >= 1u) tb = __ldg(itv + b);       // interval for row b

        bool odd = (b & 1u) != 0u;
        #pragma unroll 8
        for (unsigned c = 0; c < chunks; ++c) {
            unsigned fi = c * 256u + tid;
            float4 v = make_float4(1.f, 1.f, 1.f, 1.f);
            if (b >= 2u) {
                if (fi == fs) {
                    if (odd) { v.z = tb.x; v.w = tb.y; }
                    else     { v.x = tb.x; v.y = tb.y; }
                }
            } else if (b == 1u && fi == 0u) {
                v.z = tb.x; v.w = tb.y;         // row 1 of block 1 = intervals[1]
            }
            // fi==0 x,y: coeff placeholder (overwritten by finalize)
            __stcs(dst + fi, v);
        }
    } else {                                    // degree section: all ones
        float4 v = make_float4(1.f, 1.f, 1.f, 1.f);
        #pragma unroll 8
        for (unsigned c = 0; c < chunks; ++c)
            __stcs(dst + c * 256u + tid, v);
    }
}

// ---- Kernel B: warp-per-2-columns fold + bias + coeff rows ------------------
__global__ void __launch_bounds__(256) finalize(
    const float* __restrict__ bias,
    const float2* __restrict__ itv,
    float* __restrict__ out,
    int ncols, int n_vars)
{
    int warp = (blockIdx.x * 256 + threadIdx.x) >> 5;   // warp handles 2 columns
    int lane = threadIdx.x & 31;
    int j0 = 2 * warp;
    if (j0 >= ncols) return;
    int j1 = j0 + 1;
    bool has1 = (j1 < ncols);

    // 8 independent DRAM loads issued up front (MLP=8)
    const float* pu0 = g_part_u + (size_t)j0 * KSPLIT;
    const float* po0 = g_part_o + (size_t)j0 * KSPLIT;
    const float* pu1 = pu0 + KSPLIT;
    const float* po1 = po0 + KSPLIT;

    float a0 = __ldg(pu0 + lane);
    float a1 = __ldg(pu0 + lane + 32);
    float b0 = __ldg(po0 + lane);
    float b1 = __ldg(po0 + lane + 32);
    float c0 = 0.f, c1 = 0.f, d0 = 0.f, d1 = 0.f;
    if (has1) {
        c0 = __ldg(pu1 + lane);
        c1 = __ldg(pu1 + lane + 32);
        d0 = __ldg(po1 + lane);
        d1 = __ldg(po1 + lane + 32);
    }

    float su0 = a0 + a1, so0 = b0 + b1;
    float su1 = c0 + c1, so1 = d0 + d1;

    #pragma unroll
    for (int off = 16; off > 0; off >>= 1) {
        su0 += __shfl_xor_sync(0xFFFFFFFFu, su0, off);
        so0 += __shfl_xor_sync(0xFFFFFFFFu, so0, off);
        su1 += __shfl_xor_sync(0xFFFFFFFFu, su1, off);
        so1 += __shfl_xor_sync(0xFFFFFFFFu, so1, off);
    }

    if (lane == 0) {
        float bs = bias[0];
        size_t NE2 = (size_t)ncols * (size_t)n_vars;   // float2s per ibf array
        float2* o2 = reinterpret_cast<float2*>(out);

        {   // column j0
            float su = su0 + bs, so = so0 + bs;
            float2 vu, vo;
            if (j0 == 0) {
                float2 t0 = __ldg(itv);
                vu = make_float2(su * t0.x, su * t0.y);
                vo = make_float2(so * t0.x, so * t0.y);
            } else {
                vu = make_float2(su, su);
                vo = make_float2(so, so);
            }
            o2[(size_t)j0 * (size_t)n_vars]       = vu;
            o2[NE2 + (size_t)j0 * (size_t)n_vars] = vo;
        }
        if (has1) {   // column j1 (never 0)
            float su = su1 + bs, so = so1 + bs;
            o2[(size_t)j1 * (size_t)n_vars]       = make_float2(su, su);
            o2[NE2 + (size_t)j1 * (size_t)n_vars] = make_float2(so, so);
        }
    }
}

// ---------------------------------------------------------------------------
extern "C" void kernel_launch(void* const* d_in, const int* in_sizes, int n_in,
                              void* d_out, int out_size)
{
    const float* U    = (const float*)d_in[0];   // layer_inputs_under  (K, n+1)
    const float* O    = (const float*)d_in[1];   // layer_inputs_over   (K, n+1)
    const float* itv  = (const float*)d_in[4];   // intervals (n, 2)
    const float* pw   = (const float*)d_in[5];   // node_pos_weights (K,)
    const float* nw   = (const float*)d_in[6];   // node_neg_weights (K,)
    const float* bias = (const float*)d_in[7];   // node_bias (1,)
    float* out = (float*)d_out;

    const int n_vars = in_sizes[2];              // 4096
    const int K      = in_sizes[5];              // 4096
    const int ncols  = n_vars + 1;

    // reduction geometry
    const int RX  = (ncols + 255) / 256;
    const int rpb = (K + KSPLIT - 1) / KSPLIT;
    const unsigned RBLOCKS = (unsigned)(RX * KSPLIT);

    // fill geometry: one section = `half` float4s = one output block; the two
    // degree vectors together are exactly one more section of ones.
    unsigned half = (unsigned)(n_vars >> 1);               // float4s per section
    unsigned nsec = (unsigned)(2 * ncols) + 1u;            // 2*ncols ibf + 1 degree

    dim3 gridA(RBLOCKS + nsec);
    fused_reduce_fill<<<gridA, 256>>>(U, O, pw, nw, (const float2*)itv, out,
                                      K, ncols, rpb, RX, RBLOCKS,
                                      half, nsec);

    // one warp per 2 columns
    int nwarps = (ncols + 1) / 2;
    finalize<<<(nwarps * 32 + 255) / 256, 256>>>(bias, (const float2*)itv, out,
                                                 ncols, n_vars);
}

// round 17
// speedup vs baseline: 1.0251x; 1.0213x over previous
#include <cuda_runtime.h>

// ---------------------------------------------------------------------------
// NodeModule_4432406249918  (GB300 / sm_103a)
//   Kernel A: fused reduce + section-per-block fill.
//     - Reduce blocks: column reductions; finish with two fence-free REDG
//       atomicAdds into g_cu/g_co (LTS-coherent, no partial arrays).
//     - Fill blocks: R15-identical section fill (one section per block,
//       sequential STG.128 of ones with <=1 special float4).
//   Kernel B: tiny finalize — read L2-resident sums, +bias, write coeff rows,
//             reset sums to zero for the next graph replay.
//
// out = [ input_under ((n+1)*n,2) | input_over ((n+1)*n,2) | ones(n) | ones(n) ]
//   under_coeffs[j] = sum_k ( nw[k]*Over[k][j] + pw[k]*Under[k][j] ) + bias
//   over_coeffs [j] = sum_k ( pw[k]*Over[k][j] + nw[k]*Under[k][j] ) + bias
//   block b, row i, col c:
//     i==0           -> coeffs[b] * (b==0 ? intervals[0][c] : 1)
//     i==b (0<i<n)   -> intervals[i][c]
//     else           -> 1
// ---------------------------------------------------------------------------

#define KSPLIT 64
#define MAXC   8192   // >= n_vars+1

__device__ float g_cu[MAXC];   // zero-init; finalize self-resets each run
__device__ float g_co[MAXC];

// ---- Kernel A: fused partial reductions (atomic accumulate) + fill ----------
__global__ void __launch_bounds__(256) fused_reduce_fill(
    const float* __restrict__ U,
    const float* __restrict__ O,
    const float* __restrict__ pw,
    const float* __restrict__ nw,
    const float2* __restrict__ itv,
    float* __restrict__ out,
    int K, int ncols, int rpb, int RX, unsigned RBLOCKS,
    unsigned half, unsigned nsec)
{
    unsigned bid = blockIdx.x;

    if (bid < RBLOCKS) {
        // ---------------- reduction part (read-bound) ----------------
        int bx = (int)(bid % (unsigned)RX);
        int by = (int)(bid / (unsigned)RX);
        int j  = bx * 256 + (int)threadIdx.x;
        if (j >= ncols) return;
        int k0 = by * rpb;
        int k1 = min(k0 + rpb, K);

        float au0 = 0.f, au1 = 0.f, ao0 = 0.f, ao1 = 0.f;
        size_t base = (size_t)k0 * (size_t)ncols + (size_t)j;
        int k = k0;
        #pragma unroll 4
        for (; k + 1 < k1; k += 2, base += 2 * (size_t)ncols) {
            float u0 = __ldg(U + base);
            float o0 = __ldg(O + base);
            float u1 = __ldg(U + base + ncols);
            float o1 = __ldg(O + base + ncols);
            float p0 = __ldg(pw + k);
            float n0 = __ldg(nw + k);
            float p1 = __ldg(pw + k + 1);
            float n1 = __ldg(nw + k + 1);
            au0 = fmaf(p0, u0, au0);  au0 = fmaf(n0, o0, au0);
            ao0 = fmaf(n0, u0, ao0);  ao0 = fmaf(p0, o0, ao0);
            au1 = fmaf(p1, u1, au1);  au1 = fmaf(n1, o1, au1);
            ao1 = fmaf(n1, u1, ao1);  ao1 = fmaf(p1, o1, ao1);
        }
        if (k < k1) {
            float u = __ldg(U + base), o = __ldg(O + base);
            float p = __ldg(pw + k),   n = __ldg(nw + k);
            au0 = fmaf(p, u, au0);  au0 = fmaf(n, o, au0);
            ao0 = fmaf(n, u, ao0);  ao0 = fmaf(p, o, ao0);
        }
        // fence-free LTS-coherent accumulation (REDG; no partial arrays)
        atomicAdd(&g_cu[j], au0 + au1);
        atomicAdd(&g_co[j], ao0 + ao1);
        return;
    }

    // ---------------- fill part: one section per block (R15-identical) -------
    unsigned s = bid - RBLOCKS;                 // section index (< nsec)
    float4* dst = reinterpret_cast<float4*>(out) + (size_t)s * half;
    unsigned chunks = half >> 8;                // stores per thread
    unsigned tid = threadIdx.x;

    if (s < nsec - 1u) {                        // ibf sections (under then over)
        unsigned b  = s;                        // block index within array
        if (b >= (unsigned)ncols) b -= (unsigned)ncols;
        unsigned fs = b >> 1;                   // special float4 (rows b), b>=2
        float2 tb = make_float2(1.f, 1.f);
        if (b >= 1u) tb = __ldg(itv + b);       // interval for row b

        bool odd = (b & 1u) != 0u;
        #pragma unroll 8
        for (unsigned c = 0; c < chunks; ++c) {
            unsigned fi = c * 256u + tid;
            float4 v = make_float4(1.f, 1.f, 1.f, 1.f);
            if (b >= 2u) {
                if (fi == fs) {
                    if (odd) { v.z = tb.x; v.w = tb.y; }
                    else     { v.x = tb.x; v.y = tb.y; }
                }
            } else if (b == 1u && fi == 0u) {
                v.z = tb.x; v.w = tb.y;         // row 1 of block 1 = intervals[1]
            }
            // fi==0 x,y: coeff placeholder (overwritten by finalize)
            __stcs(dst + fi, v);
        }
    } else {                                    // degree section: all ones
        float4 v = make_float4(1.f, 1.f, 1.f, 1.f);
        #pragma unroll 8
        for (unsigned c = 0; c < chunks; ++c)
            __stcs(dst + c * 256u + tid, v);
    }
}

// ---- Kernel B: tiny finalize — L2-resident sums -> coeff rows; self-reset ---
__global__ void __launch_bounds__(256) finalize(
    const float* __restrict__ bias,
    const float2* __restrict__ itv,
    float* __restrict__ out,
    int ncols, int n_vars)
{
    int t = blockIdx.x * 256 + threadIdx.x;
    if (t >= 2 * ncols) return;
    int a = (t >= ncols) ? 1 : 0;            // 0 = under, 1 = over
    int j = t - a * ncols;

    float s = a ? g_co[j] : g_cu[j];         // L2 hit (written by atomics)
    float c = s + bias[0];

    float2 vv;
    if (j == 0) { float2 t0 = __ldg(itv); vv = make_float2(c * t0.x, c * t0.y); }
    else        {                          vv = make_float2(c, c);              }

    size_t NE2 = (size_t)ncols * (size_t)n_vars;   // float2s per ibf array
    reinterpret_cast<float2*>(out)[(size_t)a * NE2 + (size_t)j * (size_t)n_vars] = vv;

    // reset accumulator for the next graph replay (after the read above)
    if (a) g_co[j] = 0.f; else g_cu[j] = 0.f;
}

// ---------------------------------------------------------------------------
extern "C" void kernel_launch(void* const* d_in, const int* in_sizes, int n_in,
                              void* d_out, int out_size)
{
    const float* U    = (const float*)d_in[0];   // layer_inputs_under  (K, n+1)
    const float* O    = (const float*)d_in[1];   // layer_inputs_over   (K, n+1)
    const float* itv  = (const float*)d_in[4];   // intervals (n, 2)
    const float* pw   = (const float*)d_in[5];   // node_pos_weights (K,)
    const float* nw   = (const float*)d_in[6];   // node_neg_weights (K,)
    const float* bias = (const float*)d_in[7];   // node_bias (1,)
    float* out = (float*)d_out;

    const int n_vars = in_sizes[2];              // 4096
    const int K      = in_sizes[5];              // 4096
    const int ncols  = n_vars + 1;

    // reduction geometry
    const int RX  = (ncols + 255) / 256;
    const int rpb = (K + KSPLIT - 1) / KSPLIT;
    const unsigned RBLOCKS = (unsigned)(RX * KSPLIT);

    // fill geometry: one section = `half` float4s = one output block; the two
    // degree vectors together are exactly one more section of ones.
    unsigned half = (unsigned)(n_vars >> 1);               // float4s per section
    unsigned nsec = (unsigned)(2 * ncols) + 1u;            // 2*ncols ibf + 1 degree

    dim3 gridA(RBLOCKS + nsec);
    fused_reduce_fill<<<gridA, 256>>>(U, O, pw, nw, (const float2*)itv, out,
                                      K, ncols, rpb, RX, RBLOCKS,
                                      half, nsec);

    finalize<<<(2 * ncols + 255) / 256, 256>>>(bias, (const float2*)itv, out,
                                               ncols, n_vars);
}